// round 13
// baseline (speedup 1.0000x reference)
#include <cuda_runtime.h>
#include <cuda_bf16.h>
#include <cstdint>

// Problem constants
#define B_  64
#define T_  512
#define D_  128
#define R_  2048
static constexpr float HSTEP = 0.5f;
static constexpr float CLAMP_ = 5.0f;

// Device scratch
__device__ float g_proj[(size_t)B_ * T_ * R_];                 // 256 MB
__device__ __nv_bfloat16 g_B2h[(size_t)D_ * R_];               // read_W bf16 planes [N=128, K=2048]
__device__ __nv_bfloat16 g_B2l[(size_t)D_ * R_];

__device__ __forceinline__ float clampf(float v) {
    return fminf(fmaxf(v, -CLAMP_), CLAMP_);
}

// ---------------------------------------------------------------------------
// Baseline-PTX helpers (bench ptxas targets sm_103: no 'a'-suffix features)
// ---------------------------------------------------------------------------
__device__ __forceinline__ uint32_t smem_u32(const void* p) {
    uint32_t a;
    asm("{ .reg .u64 t; cvta.to.shared.u64 t, %1; cvt.u32.u64 %0, t; }" : "=r"(a) : "l"(p));
    return a;
}
__device__ __forceinline__ void cp_async16(uint32_t dst, const void* src) {
    asm volatile("cp.async.ca.shared.global [%0], [%1], 16;" :: "r"(dst), "l"(src) : "memory");
}
#define CP_COMMIT() asm volatile("cp.async.commit_group;" ::: "memory")
#define CP_WAIT(n)  asm volatile("cp.async.wait_group %0;" :: "n"(n) : "memory")

__device__ __forceinline__ void ldsm_x4(uint32_t addr, uint32_t& r0, uint32_t& r1,
                                        uint32_t& r2, uint32_t& r3) {
    asm volatile("ldmatrix.sync.aligned.m8n8.x4.shared.b16 {%0,%1,%2,%3}, [%4];"
                 : "=r"(r0), "=r"(r1), "=r"(r2), "=r"(r3) : "r"(addr));
}
__device__ __forceinline__ void mma_bf16(float* c, const uint32_t* a, uint32_t b0, uint32_t b1) {
    asm volatile(
        "mma.sync.aligned.m16n8k16.row.col.f32.bf16.bf16.f32 "
        "{%0,%1,%2,%3}, {%4,%5,%6,%7}, {%8,%9}, {%0,%1,%2,%3};"
        : "+f"(c[0]), "+f"(c[1]), "+f"(c[2]), "+f"(c[3])
        : "r"(a[0]), "r"(a[1]), "r"(a[2]), "r"(a[3]), "r"(b0), "r"(b1));
}

#define SWZ(off) ((off) ^ (((off) >> 3) & 0x70))

// ---------------------------------------------------------------------------
// Phase 1: input oscillator recurrence. One thread per (b, d).
// ---------------------------------------------------------------------------
__global__ void k_input_osc(const float* __restrict__ inputs,
                            const float* __restrict__ omega,
                            const float* __restrict__ gamma_,
                            const float* __restrict__ alpha,
                            float* __restrict__ x_in_all) {
    int idx = blockIdx.x * blockDim.x + threadIdx.x;
    int d = idx % D_;
    int b = idx / D_;
    float om  = fabsf(omega[d]);
    float ga  = fabsf(gamma_[d]);
    float al  = alpha[d];
    float om2 = om * om;
    float g2  = 2.0f * ga;
    float x = 0.0f, y = 0.0f;
    const float* inp = inputs + (size_t)b * T_ * D_ + d;
    float*       out = x_in_all + (size_t)b * T_ * D_ + d;
#pragma unroll 4
    for (int t = 0; t < T_; t++) {
        float f  = inp[t * D_];
        float ac = al * f - g2 * y - om2 * x;
        float xn = clampf(x + HSTEP * y);
        float yn = clampf(y + HSTEP * ac);
        x = xn; y = yn;
        out[t * D_] = x;
    }
}

// ---------------------------------------------------------------------------
// Weight split (GEMM2 only): W [K,N] fp32 row-major -> Dh/Dl [N,K] bf16
// ---------------------------------------------------------------------------
__global__ void k_split_bf16(const float* __restrict__ W,
                             __nv_bfloat16* __restrict__ Dh,
                             __nv_bfloat16* __restrict__ Dl,
                             int K, int N) {
    int idx = blockIdx.x * blockDim.x + threadIdx.x;
    if (idx >= K * N) return;
    int n = idx % N, k = idx / N;
    float v = W[idx];
    __nv_bfloat16 h = __float2bfloat16_rn(v);
    __nv_bfloat16 l = __float2bfloat16_rn(v - __bfloat162float(h));
    Dh[(size_t)n * K + k] = h;
    Dl[(size_t)n * K + k] = l;
}

// ---------------------------------------------------------------------------
// Phase 3: reservoir + output oscillators, float2-vectorized over r.
// ---------------------------------------------------------------------------
__global__ void k_res_out_osc_v2(const float2* __restrict__ proj,
                                 const float2* __restrict__ r_om, const float2* __restrict__ r_ga,
                                 const float2* __restrict__ r_al,
                                 const float2* __restrict__ o_om, const float2* __restrict__ o_ga,
                                 const float2* __restrict__ o_al,
                                 float2* __restrict__ x_res_all,
                                 float2* __restrict__ x_out_all) {
    constexpr int R2 = R_ / 2;  // 1024
    int idx = blockIdx.x * blockDim.x + threadIdx.x;
    int r2 = idx % R2;
    int b  = idx / R2;

    float2 romv = r_om[r2], rgav = r_ga[r2], ralv = r_al[r2];
    float2 oomv = o_om[r2], ogav = o_ga[r2], oalv = o_al[r2];
    float rom2[2], rg2[2], ral[2], oom2[2], og2[2], oal[2];
    {
        float v;
        v = fabsf(romv.x); rom2[0] = v * v; v = fabsf(romv.y); rom2[1] = v * v;
        rg2[0] = 2.0f * fabsf(rgav.x); rg2[1] = 2.0f * fabsf(rgav.y);
        ral[0] = ralv.x; ral[1] = ralv.y;
        v = fabsf(oomv.x); oom2[0] = v * v; v = fabsf(oomv.y); oom2[1] = v * v;
        og2[0] = 2.0f * fabsf(ogav.x); og2[1] = 2.0f * fabsf(ogav.y);
        oal[0] = oalv.x; oal[1] = oalv.y;
    }

    float xr[2] = {}, yr[2] = {}, xo[2] = {}, yo[2] = {};
    const float2* pp  = proj      + (size_t)b * T_ * R2 + r2;
    float2*       xra = x_res_all + (size_t)b * T_ * R2 + r2;
    float2*       xoa = x_out_all + (size_t)b * T_ * R2 + r2;

#pragma unroll 4
    for (int t = 0; t < T_; t++) {
        float2 fv = pp[t * R2];
        float f[2] = {fv.x, fv.y};
        float xrs[2], xos[2];
#pragma unroll
        for (int i = 0; i < 2; i++) {
            float acr = ral[i] * f[i] - rg2[i] * yr[i] - rom2[i] * xr[i];
            float xrn = clampf(xr[i] + HSTEP * yr[i]);
            float yrn = clampf(yr[i] + HSTEP * acr);
            xr[i] = xrn; yr[i] = yrn;
            float aco = oal[i] * xr[i] - og2[i] * yo[i] - oom2[i] * xo[i];
            float xon = clampf(xo[i] + HSTEP * yo[i]);
            float yon = clampf(yo[i] + HSTEP * aco);
            xo[i] = xon; yo[i] = yon;
            xrs[i] = xr[i]; xos[i] = xo[i];
        }
        xra[t * R2] = make_float2(xrs[0], xrs[1]);
        xoa[t * R2] = make_float2(xos[0], xos[1]);
    }
}

// ---------------------------------------------------------------------------
// GEMM1: K=128-specialized fp32 SIMT GEMM (precision-critical proj path —
// must be genuine fp32 FFMA; see decorrelation-cliff note in earlier rounds).
// C[M,N] = A[M,128] @ B[128,N] + bias[N].
// Entire K extent resident: As[128k][132m] + Bs[128k][128n] = 133 KB dyn smem,
// ONE __syncthreads, zero-sync unrolled mainloop. 256 thr, 8x8 microtile.
// Per-thread accumulation is k-ascending — same order class as prior passing
// fp32 kernels.
// ---------------------------------------------------------------------------
__global__ __launch_bounds__(256) void sgemm_k128(const float* __restrict__ A,
                                                  const float* __restrict__ Bm,
                                                  const float* __restrict__ bias,
                                                  float* __restrict__ C,
                                                  int M, int N) {
    extern __shared__ char smem[];
    float* As = (float*)smem;                    // [128][132]
    float* Bs = (float*)(smem + 128 * 132 * 4);  // [128][128]

    const int tid = threadIdx.x;
    const int rowBase = blockIdx.y * 128;
    const int colBase = blockIdx.x * 128;

    // ---- load B tile [k][n] (L2-resident: B is 1 MB total) ----
#pragma unroll
    for (int i = 0; i < 16; i++) {
        int u = tid + 256 * i;
        int k = u >> 5;
        int n4 = (u & 31) * 4;
        *(float4*)&Bs[k * 128 + n4] = *(const float4*)(Bm + (size_t)k * N + colBase + n4);
    }
    // ---- load A tile transposed -> As[k][m] ----
    {
        const int aRow = tid >> 2;        // 0..63
        const int aCol = (tid & 3) * 4;   // 0,4,8,12
#pragma unroll
        for (int half = 0; half < 2; half++) {
            int row = half * 64 + aRow;
            const float* ap = A + (size_t)(rowBase + row) * 128;
#pragma unroll
            for (int kc = 0; kc < 8; kc++) {
                float4 v = *(const float4*)(ap + kc * 16 + aCol);
                int k = kc * 16 + aCol;
                As[(k + 0) * 132 + row] = v.x;
                As[(k + 1) * 132 + row] = v.y;
                As[(k + 2) * 132 + row] = v.z;
                As[(k + 3) * 132 + row] = v.w;
            }
        }
    }
    __syncthreads();

    // ---- mainloop: zero syncs, full K ----
    const int tm = (tid >> 4) * 8;
    const int tn = (tid & 15) * 8;
    float acc[8][8] = {};
#pragma unroll 16
    for (int k = 0; k < 128; k++) {
        float4 ra0 = *(const float4*)&As[k * 132 + tm];
        float4 ra1 = *(const float4*)&As[k * 132 + tm + 4];
        float4 rb0 = *(const float4*)&Bs[k * 128 + tn];
        float4 rb1 = *(const float4*)&Bs[k * 128 + tn + 4];
        float ra[8] = {ra0.x, ra0.y, ra0.z, ra0.w, ra1.x, ra1.y, ra1.z, ra1.w};
        float rb[8] = {rb0.x, rb0.y, rb0.z, rb0.w, rb1.x, rb1.y, rb1.z, rb1.w};
#pragma unroll
        for (int i = 0; i < 8; i++)
#pragma unroll
            for (int j = 0; j < 8; j++) acc[i][j] += ra[i] * rb[j];
    }

    // ---- epilogue with bias ----
    const int col0 = colBase + tn;
    float4 bz0 = *(const float4*)&bias[col0];
    float4 bz1 = *(const float4*)&bias[col0 + 4];
#pragma unroll
    for (int i = 0; i < 8; i++) {
        int row = rowBase + tm + i;
        float4 o0, o1;
        o0.x = acc[i][0] + bz0.x;
        o0.y = acc[i][1] + bz0.y;
        o0.z = acc[i][2] + bz0.z;
        o0.w = acc[i][3] + bz0.w;
        o1.x = acc[i][4] + bz1.x;
        o1.y = acc[i][5] + bz1.y;
        o1.z = acc[i][6] + bz1.z;
        o1.w = acc[i][7] + bz1.w;
        *(float4*)&C[(size_t)row * N + col0] = o0;
        *(float4*)&C[(size_t)row * N + col0 + 4] = o1;
    }
}

// ---------------------------------------------------------------------------
// GEMM2: split-bf16 mma, 3 terms (tolerant readout path) — r5/r12-validated.
// C[M,N] = A[M,K](fp32) @ W + bias; W as bf16 hi/lo planes [N,K].
// CTA 128x128, K-chunks 64, double-buffered; D += Ah*Bh + Ah*Bl + Al*Bh.
// ---------------------------------------------------------------------------
__global__ __launch_bounds__(256) void gemm_mma_split(const float* __restrict__ A,
                                                      const __nv_bfloat16* __restrict__ Bh,
                                                      const __nv_bfloat16* __restrict__ Bl,
                                                      const float* __restrict__ bias,
                                                      float* __restrict__ C,
                                                      int M, int N, int K) {
    extern __shared__ char smem[];
    const int tid  = threadIdx.x;
    const int wid  = tid >> 5;
    const int lane = tid & 31;
    const uint32_t sb = smem_u32(smem);
    const int rowBase = blockIdx.y * 128;
    const int colBase = blockIdx.x * 128;
    const int NCHUNK = K >> 6;

    auto load_chunk = [&](int c, int s) {
        const int k0 = c << 6;
        char* Ah_s = smem + s * 65536;
        char* Al_s = Ah_s + 16384;
        const uint32_t bh_u = sb + s * 65536 + 32768;
        const uint32_t bl_u = bh_u + 16384;
#pragma unroll
        for (int i = 0; i < 4; i++) {
            int u = tid + 256 * i;
            int row = u >> 3;
            int kc = (u & 7) * 8;
            const float4* src = (const float4*)(A + (size_t)(rowBase + row) * K + k0 + kc);
            float4 v0 = src[0], v1 = src[1];
            float vv[8] = {v0.x, v0.y, v0.z, v0.w, v1.x, v1.y, v1.z, v1.w};
            __nv_bfloat16 h[8], l[8];
#pragma unroll
            for (int j = 0; j < 8; j++) {
                h[j] = __float2bfloat16_rn(vv[j]);
                l[j] = __float2bfloat16_rn(vv[j] - __bfloat162float(h[j]));
            }
            uint32_t off = SWZ((uint32_t)(row * 128 + kc * 2));
            *(uint4*)(Ah_s + off) = *(const uint4*)h;
            *(uint4*)(Al_s + off) = *(const uint4*)l;
        }
#pragma unroll
        for (int i = 0; i < 4; i++) {
            int ch = tid + 256 * i;
            int row = ch >> 3;
            int kc16 = ch & 7;
            uint32_t off = SWZ((uint32_t)(row * 128 + kc16 * 16));
            const char* sh = (const char*)(Bh + (size_t)(colBase + row) * K + k0) + kc16 * 16;
            const char* sl = (const char*)(Bl + (size_t)(colBase + row) * K + k0) + kc16 * 16;
            cp_async16(bh_u + off, sh);
            cp_async16(bl_u + off, sl);
        }
    };

    const int warpM = wid & 1;
    const int warpN = wid >> 1;
    const int g = lane >> 3;
    const int r = lane & 7;

    float acc[4][4][4] = {};

    const int aRow = warpM * 64 + (g & 1) * 8 + r;
    const int aKu  = (g >> 1);
    const int bRow = warpN * 32 + (g >> 1) * 8 + r;
    const int bKu  = (g & 1);

    load_chunk(0, 0);
    CP_COMMIT();

    for (int c = 0; c < NCHUNK; c++) {
        const int s = c & 1;
        if (c + 1 < NCHUNK) {
            load_chunk(c + 1, s ^ 1);
            CP_COMMIT();
            CP_WAIT(1);
        } else {
            CP_WAIT(0);
        }
        __syncthreads();

        const uint32_t aH_b = sb + s * 65536;
        const uint32_t aL_b = aH_b + 16384;
        const uint32_t bH_b = aH_b + 32768;
        const uint32_t bL_b = aH_b + 49152;

#pragma unroll
        for (int ks = 0; ks < 4; ks++) {
            uint32_t aH[4][4], aL[4][4];
            const int ku = ks * 2 + aKu;
#pragma unroll
            for (int mb = 0; mb < 4; mb++) {
                uint32_t off = SWZ((uint32_t)((aRow + mb * 16) * 128 + ku * 16));
                ldsm_x4(aH_b + off, aH[mb][0], aH[mb][1], aH[mb][2], aH[mb][3]);
                ldsm_x4(aL_b + off, aL[mb][0], aL[mb][1], aL[mb][2], aL[mb][3]);
            }
            const int bku = ks * 2 + bKu;
#pragma unroll
            for (int nbp = 0; nbp < 2; nbp++) {
                uint32_t bh[4], bl[4];
                uint32_t boff = SWZ((uint32_t)((bRow + nbp * 16) * 128 + bku * 16));
                ldsm_x4(bH_b + boff, bh[0], bh[1], bh[2], bh[3]);
                ldsm_x4(bL_b + boff, bl[0], bl[1], bl[2], bl[3]);
#pragma unroll
                for (int h = 0; h < 2; h++) {
                    const int nb = nbp * 2 + h;
#pragma unroll
                    for (int mb = 0; mb < 4; mb++) {
                        mma_bf16(acc[mb][nb], aH[mb], bh[h * 2], bh[h * 2 + 1]);
                        mma_bf16(acc[mb][nb], aH[mb], bl[h * 2], bl[h * 2 + 1]);
                        mma_bf16(acc[mb][nb], aL[mb], bh[h * 2], bh[h * 2 + 1]);
                    }
                }
            }
        }
        __syncthreads();
    }

    // epilogue: regs -> smem stage -> coalesced GMEM with bias
    float* stage = (float*)smem;  // [128][132]
    {
        const int mr = warpM * 64 + (lane >> 2);
        const int nc = warpN * 32 + (lane & 3) * 2;
#pragma unroll
        for (int mb = 0; mb < 4; mb++) {
#pragma unroll
            for (int nb = 0; nb < 4; nb++) {
                float* p0 = &stage[(mr + mb * 16) * 132 + nc + nb * 8];
                float* p1 = &stage[(mr + mb * 16 + 8) * 132 + nc + nb * 8];
                p0[0] = acc[mb][nb][0];
                p0[1] = acc[mb][nb][1];
                p1[0] = acc[mb][nb][2];
                p1[1] = acc[mb][nb][3];
            }
        }
    }
    __syncthreads();

    const int colL = tid & 127;
    const float bz = bias[colBase + colL];
#pragma unroll
    for (int r0 = tid >> 7; r0 < 128; r0 += 2)
        C[(size_t)(rowBase + r0) * N + colBase + colL] = stage[r0 * 132 + colL] + bz;
}

// ---------------------------------------------------------------------------
// Launch. Output layout: preds | x_in_all | x_res_all | x_out_all
// ---------------------------------------------------------------------------
extern "C" void kernel_launch(void* const* d_in, const int* in_sizes, int n_in,
                              void* d_out, int out_size) {
    const float* inputs   = (const float*)d_in[0];
    const float* in_omega = (const float*)d_in[1];
    const float* in_gamma = (const float*)d_in[2];
    const float* in_alpha = (const float*)d_in[3];
    const float* proj_W   = (const float*)d_in[4];
    const float* proj_b   = (const float*)d_in[5];
    const float* res_om   = (const float*)d_in[6];
    const float* res_ga   = (const float*)d_in[7];
    const float* res_al   = (const float*)d_in[8];
    const float* out_om   = (const float*)d_in[9];
    const float* out_ga   = (const float*)d_in[10];
    const float* out_al   = (const float*)d_in[11];
    const float* read_W   = (const float*)d_in[12];
    const float* read_b   = (const float*)d_in[13];

    float* out = (float*)d_out;
    const size_t BTD = (size_t)B_ * T_ * D_;
    const size_t BTR = (size_t)B_ * T_ * R_;
    float* preds     = out;
    float* x_in_all  = out + BTD;
    float* x_res_all = out + 2 * BTD;
    float* x_out_all = out + 2 * BTD + BTR;

    void* p;
    cudaGetSymbolAddress(&p, g_proj);   float* proj = (float*)p;
    cudaGetSymbolAddress(&p, g_B2h);    __nv_bfloat16* B2h = (__nv_bfloat16*)p;
    cudaGetSymbolAddress(&p, g_B2l);    __nv_bfloat16* B2l = (__nv_bfloat16*)p;

    const int SMEM_G1 = 128 * 132 * 4 + 128 * 128 * 4;  // 133120
    const int SMEM_G2 = 2 * 65536;                       // 131072
    cudaFuncSetAttribute(sgemm_k128, cudaFuncAttributeMaxDynamicSharedMemorySize, SMEM_G1);
    cudaFuncSetAttribute(gemm_mma_split, cudaFuncAttributeMaxDynamicSharedMemorySize, SMEM_G2);

    // Phase 1: input oscillators
    k_input_osc<<<(B_ * D_) / 256, 256>>>(inputs, in_omega, in_gamma, in_alpha, x_in_all);

    // read_W split (for GEMM2 only)
    k_split_bf16<<<(R_ * D_ + 255) / 256, 256>>>(read_W, B2h, B2l, R_, D_);

    // Phase 2 (fp32 SIMT, K=128-specialized): proj = x_in @ proj_W + proj_b
    {
        dim3 grid(R_ / 128, (B_ * T_) / 128);  // (16, 256)
        sgemm_k128<<<grid, 256, SMEM_G1>>>(x_in_all, proj_W, proj_b, proj, B_ * T_, R_);
    }

    // Phase 3: reservoir + output oscillators (float2, 65536 threads)
    k_res_out_osc_v2<<<(B_ * R_ / 2) / 256, 256>>>((const float2*)proj,
                                                   (const float2*)res_om, (const float2*)res_ga,
                                                   (const float2*)res_al,
                                                   (const float2*)out_om, (const float2*)out_ga,
                                                   (const float2*)out_al,
                                                   (float2*)x_res_all, (float2*)x_out_all);

    // Phase 4 (split-bf16 tensor cores, tolerant): preds = x_out @ read_W + read_b
    {
        dim3 grid(D_ / 128, (B_ * T_) / 128);  // (1, 256)
        gemm_mma_split<<<grid, 256, SMEM_G2>>>(x_out_all, B2h, B2l, read_b, preds,
                                               B_ * T_, D_, R_);
    }
}

// round 16
// speedup vs baseline: 1.0903x; 1.0903x over previous
#include <cuda_runtime.h>
#include <cuda_bf16.h>
#include <cstdint>

// Problem constants
#define B_  64
#define T_  512
#define D_  128
#define R_  2048
static constexpr float HSTEP = 0.5f;
static constexpr float CLAMP_ = 5.0f;

// Device scratch
__device__ float g_proj[(size_t)B_ * T_ * R_];                 // 256 MB
__device__ __nv_bfloat16 g_B2h[(size_t)D_ * R_];               // read_W bf16 planes [N=128, K=2048]
__device__ __nv_bfloat16 g_B2l[(size_t)D_ * R_];

__device__ __forceinline__ float clampf(float v) {
    return fminf(fmaxf(v, -CLAMP_), CLAMP_);
}

// ---------------------------------------------------------------------------
// Baseline-PTX helpers (bench ptxas targets sm_103: no 'a'-suffix features)
// ---------------------------------------------------------------------------
__device__ __forceinline__ uint32_t smem_u32(const void* p) {
    uint32_t a;
    asm("{ .reg .u64 t; cvta.to.shared.u64 t, %1; cvt.u32.u64 %0, t; }" : "=r"(a) : "l"(p));
    return a;
}
__device__ __forceinline__ void cp_async16(uint32_t dst, const void* src) {
    asm volatile("cp.async.ca.shared.global [%0], [%1], 16;" :: "r"(dst), "l"(src) : "memory");
}
#define CP_COMMIT() asm volatile("cp.async.commit_group;" ::: "memory")
#define CP_WAIT(n)  asm volatile("cp.async.wait_group %0;" :: "n"(n) : "memory")

__device__ __forceinline__ void ldsm_x4(uint32_t addr, uint32_t& r0, uint32_t& r1,
                                        uint32_t& r2, uint32_t& r3) {
    asm volatile("ldmatrix.sync.aligned.m8n8.x4.shared.b16 {%0,%1,%2,%3}, [%4];"
                 : "=r"(r0), "=r"(r1), "=r"(r2), "=r"(r3) : "r"(addr));
}
__device__ __forceinline__ void mma_bf16(float* c, const uint32_t* a, uint32_t b0, uint32_t b1) {
    asm volatile(
        "mma.sync.aligned.m16n8k16.row.col.f32.bf16.bf16.f32 "
        "{%0,%1,%2,%3}, {%4,%5,%6,%7}, {%8,%9}, {%0,%1,%2,%3};"
        : "+f"(c[0]), "+f"(c[1]), "+f"(c[2]), "+f"(c[3])
        : "r"(a[0]), "r"(a[1]), "r"(a[2]), "r"(a[3]), "r"(b0), "r"(b1));
}

#define SWZ(off) ((off) ^ (((off) >> 3) & 0x70))

// ---------------------------------------------------------------------------
// Phase 1: input oscillator recurrence. One thread per (b, d).
// ---------------------------------------------------------------------------
__global__ void k_input_osc(const float* __restrict__ inputs,
                            const float* __restrict__ omega,
                            const float* __restrict__ gamma_,
                            const float* __restrict__ alpha,
                            float* __restrict__ x_in_all) {
    int idx = blockIdx.x * blockDim.x + threadIdx.x;
    int d = idx % D_;
    int b = idx / D_;
    float om  = fabsf(omega[d]);
    float ga  = fabsf(gamma_[d]);
    float al  = alpha[d];
    float om2 = om * om;
    float g2  = 2.0f * ga;
    float x = 0.0f, y = 0.0f;
    const float* inp = inputs + (size_t)b * T_ * D_ + d;
    float*       out = x_in_all + (size_t)b * T_ * D_ + d;
#pragma unroll 4
    for (int t = 0; t < T_; t++) {
        float f  = inp[t * D_];
        float ac = al * f - g2 * y - om2 * x;
        float xn = clampf(x + HSTEP * y);
        float yn = clampf(y + HSTEP * ac);
        x = xn; y = yn;
        out[t * D_] = x;
    }
}

// ---------------------------------------------------------------------------
// Weight split (GEMM2 only): W [K,N] fp32 row-major -> Dh/Dl [N,K] bf16
// ---------------------------------------------------------------------------
__global__ void k_split_bf16(const float* __restrict__ W,
                             __nv_bfloat16* __restrict__ Dh,
                             __nv_bfloat16* __restrict__ Dl,
                             int K, int N) {
    int idx = blockIdx.x * blockDim.x + threadIdx.x;
    if (idx >= K * N) return;
    int n = idx % N, k = idx / N;
    float v = W[idx];
    __nv_bfloat16 h = __float2bfloat16_rn(v);
    __nv_bfloat16 l = __float2bfloat16_rn(v - __bfloat162float(h));
    Dh[(size_t)n * K + k] = h;
    Dl[(size_t)n * K + k] = l;
}

// ---------------------------------------------------------------------------
// Phase 3: reservoir + output oscillators, SCALAR over r (131072 threads ->
// ~28 warps/SM, 2x r12's occupancy). Per-element arithmetic identical to the
// validated float2/float4 versions; loads/stores fully coalesced (128B/warp).
// ---------------------------------------------------------------------------
__global__ void k_res_out_osc_s(const float* __restrict__ proj,
                                const float* __restrict__ r_om, const float* __restrict__ r_ga,
                                const float* __restrict__ r_al,
                                const float* __restrict__ o_om, const float* __restrict__ o_ga,
                                const float* __restrict__ o_al,
                                float* __restrict__ x_res_all,
                                float* __restrict__ x_out_all) {
    int idx = blockIdx.x * blockDim.x + threadIdx.x;  // b*R + r
    int r = idx % R_;
    int b = idx / R_;

    float v;
    v = fabsf(r_om[r]);
    const float rom2 = v * v;
    const float rg2  = 2.0f * fabsf(r_ga[r]);
    const float ral  = r_al[r];
    v = fabsf(o_om[r]);
    const float oom2 = v * v;
    const float og2  = 2.0f * fabsf(o_ga[r]);
    const float oal  = o_al[r];

    float xr = 0.0f, yr = 0.0f, xo = 0.0f, yo = 0.0f;
    const float* pp  = proj      + (size_t)b * T_ * R_ + r;
    float*       xra = x_res_all + (size_t)b * T_ * R_ + r;
    float*       xoa = x_out_all + (size_t)b * T_ * R_ + r;

#pragma unroll 4
    for (int t = 0; t < T_; t++) {
        float f = pp[t * R_];
        float acr = ral * f - rg2 * yr - rom2 * xr;
        float xrn = clampf(xr + HSTEP * yr);
        float yrn = clampf(yr + HSTEP * acr);
        xr = xrn; yr = yrn;
        float aco = oal * xr - og2 * yo - oom2 * xo;
        float xon = clampf(xo + HSTEP * yo);
        float yon = clampf(yo + HSTEP * aco);
        xo = xon; yo = yon;
        xra[t * R_] = xr;
        xoa[t * R_] = xo;
    }
}

// ---------------------------------------------------------------------------
// GEMM1: fp32 SIMT (precision-critical — proj feeds a clamped chaotic
// recurrence with a decorrelation cliff at ~1e-6 proj deviation; only genuine
// fp32 FFMA stays under it). r12-validated configuration: BM=BN=128, BK=16,
// 256 threads, 8x8 microtile, double-buffered smem, 2 CTAs/SM.
// ---------------------------------------------------------------------------
__global__ __launch_bounds__(256, 2) void sgemm_bias_v2(const float* __restrict__ A,
                                                        const float* __restrict__ Bm,
                                                        const float* __restrict__ bias,
                                                        float* __restrict__ C,
                                                        int M, int N, int K) {
    constexpr int BK = 16;
    __shared__ float As[2][BK][128 + 4];
    __shared__ float Bs[2][BK][128];

    const int tid = threadIdx.x;
    const int rowBase = blockIdx.y * 128;
    const int colBase = blockIdx.x * 128;

    const int aRow = tid >> 2;
    const int aCol = (tid & 3) * 4;
    const int bRow = tid >> 5;
    const int bCol = (tid & 31) * 4;

    const float* Aptr0 = A + (size_t)(rowBase + aRow) * K + aCol;
    const float* Aptr1 = Aptr0 + (size_t)64 * K;
    const float* Bptr0 = Bm + (size_t)bRow * N + colBase + bCol;
    const float* Bptr1 = Bptr0 + (size_t)8 * N;

    const int tm = (tid >> 4) * 8;
    const int tn = (tid & 15) * 8;

    float acc[8][8] = {};
    float4 pa0, pa1, pb0, pb1;

    pa0 = *(const float4*)(Aptr0);
    pa1 = *(const float4*)(Aptr1);
    pb0 = *(const float4*)(Bptr0);
    pb1 = *(const float4*)(Bptr1);
    {
        As[0][aCol + 0][aRow] = pa0.x;
        As[0][aCol + 1][aRow] = pa0.y;
        As[0][aCol + 2][aRow] = pa0.z;
        As[0][aCol + 3][aRow] = pa0.w;
        As[0][aCol + 0][aRow + 64] = pa1.x;
        As[0][aCol + 1][aRow + 64] = pa1.y;
        As[0][aCol + 2][aRow + 64] = pa1.z;
        As[0][aCol + 3][aRow + 64] = pa1.w;
        *(float4*)&Bs[0][bRow][bCol] = pb0;
        *(float4*)&Bs[0][bRow + 8][bCol] = pb1;
    }
    __syncthreads();

    int buf = 0;
    for (int k0 = 0; k0 < K; k0 += BK) {
        const int knext = k0 + BK;
        if (knext < K) {
            pa0 = *(const float4*)(Aptr0 + knext);
            pa1 = *(const float4*)(Aptr1 + knext);
            pb0 = *(const float4*)(Bptr0 + (size_t)knext * N);
            pb1 = *(const float4*)(Bptr1 + (size_t)knext * N);
        }
#pragma unroll
        for (int k = 0; k < BK; k++) {
            float4 ra0 = *(const float4*)&As[buf][k][tm];
            float4 ra1 = *(const float4*)&As[buf][k][tm + 4];
            float4 rb0 = *(const float4*)&Bs[buf][k][tn];
            float4 rb1 = *(const float4*)&Bs[buf][k][tn + 4];
            float ra[8] = {ra0.x, ra0.y, ra0.z, ra0.w, ra1.x, ra1.y, ra1.z, ra1.w};
            float rb[8] = {rb0.x, rb0.y, rb0.z, rb0.w, rb1.x, rb1.y, rb1.z, rb1.w};
#pragma unroll
            for (int i = 0; i < 8; i++)
#pragma unroll
                for (int j = 0; j < 8; j++) acc[i][j] += ra[i] * rb[j];
        }
        if (knext < K) {
            int nb = buf ^ 1;
            As[nb][aCol + 0][aRow] = pa0.x;
            As[nb][aCol + 1][aRow] = pa0.y;
            As[nb][aCol + 2][aRow] = pa0.z;
            As[nb][aCol + 3][aRow] = pa0.w;
            As[nb][aCol + 0][aRow + 64] = pa1.x;
            As[nb][aCol + 1][aRow + 64] = pa1.y;
            As[nb][aCol + 2][aRow + 64] = pa1.z;
            As[nb][aCol + 3][aRow + 64] = pa1.w;
            *(float4*)&Bs[nb][bRow][bCol] = pb0;
            *(float4*)&Bs[nb][bRow + 8][bCol] = pb1;
            __syncthreads();
            buf = nb;
        }
    }

    const int col0 = colBase + tn;
    float4 bz0 = *(const float4*)&bias[col0];
    float4 bz1 = *(const float4*)&bias[col0 + 4];
#pragma unroll
    for (int i = 0; i < 8; i++) {
        int row = rowBase + tm + i;
        float4 o0, o1;
        o0.x = acc[i][0] + bz0.x;
        o0.y = acc[i][1] + bz0.y;
        o0.z = acc[i][2] + bz0.z;
        o0.w = acc[i][3] + bz0.w;
        o1.x = acc[i][4] + bz1.x;
        o1.y = acc[i][5] + bz1.y;
        o1.z = acc[i][6] + bz1.z;
        o1.w = acc[i][7] + bz1.w;
        *(float4*)&C[(size_t)row * N + col0] = o0;
        *(float4*)&C[(size_t)row * N + col0 + 4] = o1;
    }
}

// ---------------------------------------------------------------------------
// GEMM2: split-bf16 mma, 3 terms (tolerant readout path), SINGLE-stage smem
// (66 KB) so 2 CTAs/SM co-reside: all 256 CTAs land in ONE wave and the
// co-resident CTA's mma covers the other's load phase. Same mma sequence and
// accumulation order as the r5/r12-validated double-buffered version.
// C[M,N] = A[M,K](fp32) @ W + bias; W as bf16 hi/lo planes [N,K].
// ---------------------------------------------------------------------------
__global__ __launch_bounds__(256, 2) void gemm_mma_split_1s(const float* __restrict__ A,
                                                            const __nv_bfloat16* __restrict__ Bh,
                                                            const __nv_bfloat16* __restrict__ Bl,
                                                            const float* __restrict__ bias,
                                                            float* __restrict__ C,
                                                            int M, int N, int K) {
    extern __shared__ char smem[];
    const int tid  = threadIdx.x;
    const int wid  = tid >> 5;
    const int lane = tid & 31;
    const uint32_t sb = smem_u32(smem);
    const int rowBase = blockIdx.y * 128;
    const int colBase = blockIdx.x * 128;
    const int NCHUNK = K >> 6;  // K/64

    const uint32_t aH_b = sb;
    const uint32_t aL_b = sb + 16384;
    const uint32_t bH_b = sb + 32768;
    const uint32_t bL_b = sb + 49152;

    const int warpM = wid & 1;
    const int warpN = wid >> 1;
    const int g = lane >> 3;
    const int r = lane & 7;

    float acc[4][4][4] = {};

    const int aRow = warpM * 64 + (g & 1) * 8 + r;
    const int aKu  = (g >> 1);
    const int bRow = warpN * 32 + (g >> 1) * 8 + r;
    const int bKu  = (g & 1);

    for (int c = 0; c < NCHUNK; c++) {
        const int k0 = c << 6;
        // ---- load chunk (single stage) ----
#pragma unroll
        for (int i = 0; i < 4; i++) {
            int u = tid + 256 * i;
            int row = u >> 3;
            int kc = (u & 7) * 8;
            const float4* src = (const float4*)(A + (size_t)(rowBase + row) * K + k0 + kc);
            float4 v0 = src[0], v1 = src[1];
            float vv[8] = {v0.x, v0.y, v0.z, v0.w, v1.x, v1.y, v1.z, v1.w};
            __nv_bfloat16 h[8], l[8];
#pragma unroll
            for (int j = 0; j < 8; j++) {
                h[j] = __float2bfloat16_rn(vv[j]);
                l[j] = __float2bfloat16_rn(vv[j] - __bfloat162float(h[j]));
            }
            uint32_t off = SWZ((uint32_t)(row * 128 + kc * 2));
            *(uint4*)(smem + off)         = *(const uint4*)h;
            *(uint4*)(smem + 16384 + off) = *(const uint4*)l;
        }
#pragma unroll
        for (int i = 0; i < 4; i++) {
            int ch = tid + 256 * i;
            int row = ch >> 3;
            int kc16 = ch & 7;
            uint32_t off = SWZ((uint32_t)(row * 128 + kc16 * 16));
            const char* sh = (const char*)(Bh + (size_t)(colBase + row) * K + k0) + kc16 * 16;
            const char* sl = (const char*)(Bl + (size_t)(colBase + row) * K + k0) + kc16 * 16;
            cp_async16(bH_b + off, sh);
            cp_async16(bL_b + off, sl);
        }
        CP_COMMIT();
        CP_WAIT(0);
        __syncthreads();

        // ---- mma over chunk ----
#pragma unroll
        for (int ks = 0; ks < 4; ks++) {
            uint32_t aH[4][4], aL[4][4];
            const int ku = ks * 2 + aKu;
#pragma unroll
            for (int mb = 0; mb < 4; mb++) {
                uint32_t off = SWZ((uint32_t)((aRow + mb * 16) * 128 + ku * 16));
                ldsm_x4(aH_b + off, aH[mb][0], aH[mb][1], aH[mb][2], aH[mb][3]);
                ldsm_x4(aL_b + off, aL[mb][0], aL[mb][1], aL[mb][2], aL[mb][3]);
            }
            const int bku = ks * 2 + bKu;
#pragma unroll
            for (int nbp = 0; nbp < 2; nbp++) {
                uint32_t bh[4], bl[4];
                uint32_t boff = SWZ((uint32_t)((bRow + nbp * 16) * 128 + bku * 16));
                ldsm_x4(bH_b + boff, bh[0], bh[1], bh[2], bh[3]);
                ldsm_x4(bL_b + boff, bl[0], bl[1], bl[2], bl[3]);
#pragma unroll
                for (int h = 0; h < 2; h++) {
                    const int nb = nbp * 2 + h;
#pragma unroll
                    for (int mb = 0; mb < 4; mb++) {
                        mma_bf16(acc[mb][nb], aH[mb], bh[h * 2], bh[h * 2 + 1]);
                        mma_bf16(acc[mb][nb], aH[mb], bl[h * 2], bl[h * 2 + 1]);
                        mma_bf16(acc[mb][nb], aL[mb], bh[h * 2], bh[h * 2 + 1]);
                    }
                }
            }
        }
        __syncthreads();
    }

    // ---- epilogue: regs -> smem stage -> coalesced GMEM with bias ----
    float* stage = (float*)smem;  // [128][129] = 66048 B
    {
        const int mr = warpM * 64 + (lane >> 2);
        const int nc = warpN * 32 + (lane & 3) * 2;
#pragma unroll
        for (int mb = 0; mb < 4; mb++) {
#pragma unroll
            for (int nb = 0; nb < 4; nb++) {
                float* p0 = &stage[(mr + mb * 16) * 129 + nc + nb * 8];
                float* p1 = &stage[(mr + mb * 16 + 8) * 129 + nc + nb * 8];
                p0[0] = acc[mb][nb][0];
                p0[1] = acc[mb][nb][1];
                p1[0] = acc[mb][nb][2];
                p1[1] = acc[mb][nb][3];
            }
        }
    }
    __syncthreads();

    const int colL = tid & 127;
    const float bz = bias[colBase + colL];
#pragma unroll
    for (int r0 = tid >> 7; r0 < 128; r0 += 2)
        C[(size_t)(rowBase + r0) * N + colBase + colL] = stage[r0 * 129 + colL] + bz;
}

// ---------------------------------------------------------------------------
// Launch. Output layout: preds | x_in_all | x_res_all | x_out_all
// ---------------------------------------------------------------------------
extern "C" void kernel_launch(void* const* d_in, const int* in_sizes, int n_in,
                              void* d_out, int out_size) {
    const float* inputs   = (const float*)d_in[0];
    const float* in_omega = (const float*)d_in[1];
    const float* in_gamma = (const float*)d_in[2];
    const float* in_alpha = (const float*)d_in[3];
    const float* proj_W   = (const float*)d_in[4];
    const float* proj_b   = (const float*)d_in[5];
    const float* res_om   = (const float*)d_in[6];
    const float* res_ga   = (const float*)d_in[7];
    const float* res_al   = (const float*)d_in[8];
    const float* out_om   = (const float*)d_in[9];
    const float* out_ga   = (const float*)d_in[10];
    const float* out_al   = (const float*)d_in[11];
    const float* read_W   = (const float*)d_in[12];
    const float* read_b   = (const float*)d_in[13];

    float* out = (float*)d_out;
    const size_t BTD = (size_t)B_ * T_ * D_;
    const size_t BTR = (size_t)B_ * T_ * R_;
    float* preds     = out;
    float* x_in_all  = out + BTD;
    float* x_res_all = out + 2 * BTD;
    float* x_out_all = out + 2 * BTD + BTR;

    void* p;
    cudaGetSymbolAddress(&p, g_proj);   float* proj = (float*)p;
    cudaGetSymbolAddress(&p, g_B2h);    __nv_bfloat16* B2h = (__nv_bfloat16*)p;
    cudaGetSymbolAddress(&p, g_B2l);    __nv_bfloat16* B2l = (__nv_bfloat16*)p;

    const int SMEM_G2 = 128 * 129 * 4;  // 66048 (single stage; epilogue fits)
    cudaFuncSetAttribute(gemm_mma_split_1s, cudaFuncAttributeMaxDynamicSharedMemorySize, SMEM_G2);

    // Phase 1: input oscillators
    k_input_osc<<<(B_ * D_) / 256, 256>>>(inputs, in_omega, in_gamma, in_alpha, x_in_all);

    // read_W split (for GEMM2 only)
    k_split_bf16<<<(R_ * D_ + 255) / 256, 256>>>(read_W, B2h, B2l, R_, D_);

    // Phase 2 (fp32 SIMT, r12-validated): proj = x_in @ proj_W + proj_b
    {
        dim3 grid(R_ / 128, (B_ * T_) / 128);  // (16, 256)
        sgemm_bias_v2<<<grid, 256>>>(x_in_all, proj_W, proj_b, proj, B_ * T_, R_, D_);
    }

    // Phase 3: reservoir + output oscillators (scalar, 131072 threads)
    k_res_out_osc_s<<<(B_ * R_) / 256, 256>>>(proj, res_om, res_ga, res_al,
                                              out_om, out_ga, out_al,
                                              x_res_all, x_out_all);

    // Phase 4 (split-bf16 tensor cores, single-stage, 2 CTAs/SM):
    // preds = x_out @ read_W + read_b
    {
        dim3 grid(D_ / 128, (B_ * T_) / 128);  // (1, 256)
        gemm_mma_split_1s<<<grid, 256, SMEM_G2>>>(x_out_all, B2h, B2l, read_b, preds,
                                                  B_ * T_, D_, R_);
    }
}

// round 17
// speedup vs baseline: 1.1506x; 1.0553x over previous
#include <cuda_runtime.h>
#include <cuda_bf16.h>
#include <cstdint>

// Problem constants
#define B_  64
#define T_  512
#define D_  128
#define R_  2048
static constexpr float HSTEP = 0.5f;
static constexpr float CLAMP_ = 5.0f;

// Device scratch (proj eliminated by fusion)
__device__ __nv_bfloat16 g_B2h[(size_t)D_ * R_];               // read_W bf16 planes [N=128, K=2048]
__device__ __nv_bfloat16 g_B2l[(size_t)D_ * R_];

__device__ __forceinline__ float clampf(float v) {
    return fminf(fmaxf(v, -CLAMP_), CLAMP_);
}

// ---------------------------------------------------------------------------
// Baseline-PTX helpers (bench ptxas targets sm_103: no 'a'-suffix features)
// ---------------------------------------------------------------------------
__device__ __forceinline__ uint32_t smem_u32(const void* p) {
    uint32_t a;
    asm("{ .reg .u64 t; cvta.to.shared.u64 t, %1; cvt.u32.u64 %0, t; }" : "=r"(a) : "l"(p));
    return a;
}
__device__ __forceinline__ void cp_async16(uint32_t dst, const void* src) {
    asm volatile("cp.async.ca.shared.global [%0], [%1], 16;" :: "r"(dst), "l"(src) : "memory");
}
#define CP_COMMIT() asm volatile("cp.async.commit_group;" ::: "memory")
#define CP_WAIT(n)  asm volatile("cp.async.wait_group %0;" :: "n"(n) : "memory")

__device__ __forceinline__ void ldsm_x4(uint32_t addr, uint32_t& r0, uint32_t& r1,
                                        uint32_t& r2, uint32_t& r3) {
    asm volatile("ldmatrix.sync.aligned.m8n8.x4.shared.b16 {%0,%1,%2,%3}, [%4];"
                 : "=r"(r0), "=r"(r1), "=r"(r2), "=r"(r3) : "r"(addr));
}
__device__ __forceinline__ void mma_bf16(float* c, const uint32_t* a, uint32_t b0, uint32_t b1) {
    asm volatile(
        "mma.sync.aligned.m16n8k16.row.col.f32.bf16.bf16.f32 "
        "{%0,%1,%2,%3}, {%4,%5,%6,%7}, {%8,%9}, {%0,%1,%2,%3};"
        : "+f"(c[0]), "+f"(c[1]), "+f"(c[2]), "+f"(c[3])
        : "r"(a[0]), "r"(a[1]), "r"(a[2]), "r"(a[3]), "r"(b0), "r"(b1));
}

#define SWZ(off) ((off) ^ (((off) >> 3) & 0x70))

// ---------------------------------------------------------------------------
// Phase 1: input oscillator recurrence. One thread per (b, d).
// ---------------------------------------------------------------------------
__global__ void k_input_osc(const float* __restrict__ inputs,
                            const float* __restrict__ omega,
                            const float* __restrict__ gamma_,
                            const float* __restrict__ alpha,
                            float* __restrict__ x_in_all) {
    int idx = blockIdx.x * blockDim.x + threadIdx.x;
    int d = idx % D_;
    int b = idx / D_;
    float om  = fabsf(omega[d]);
    float ga  = fabsf(gamma_[d]);
    float al  = alpha[d];
    float om2 = om * om;
    float g2  = 2.0f * ga;
    float x = 0.0f, y = 0.0f;
    const float* inp = inputs + (size_t)b * T_ * D_ + d;
    float*       out = x_in_all + (size_t)b * T_ * D_ + d;
#pragma unroll 4
    for (int t = 0; t < T_; t++) {
        float f  = inp[t * D_];
        float ac = al * f - g2 * y - om2 * x;
        float xn = clampf(x + HSTEP * y);
        float yn = clampf(y + HSTEP * ac);
        x = xn; y = yn;
        out[t * D_] = x;
    }
}

// ---------------------------------------------------------------------------
// Weight split (GEMM2 only): W [K,N] fp32 row-major -> Dh/Dl [N,K] bf16
// ---------------------------------------------------------------------------
__global__ void k_split_bf16(const float* __restrict__ W,
                             __nv_bfloat16* __restrict__ Dh,
                             __nv_bfloat16* __restrict__ Dl,
                             int K, int N) {
    int idx = blockIdx.x * blockDim.x + threadIdx.x;
    if (idx >= K * N) return;
    int n = idx % N, k = idx / N;
    float v = W[idx];
    __nv_bfloat16 h = __float2bfloat16_rn(v);
    __nv_bfloat16 l = __float2bfloat16_rn(v - __bfloat162float(h));
    Dh[(size_t)n * K + k] = h;
    Dl[(size_t)n * K + k] = l;
}

// ---------------------------------------------------------------------------
// FUSED GEMM1 + phase 3: each CTA owns (b, 128-wide r-block) and walks the 4
// t-chunks sequentially. Per chunk: exact r12 sgemm_bias_v2 mainloop (fp32
// FFMA, identical k-order -> bit-identical proj values; precision-critical
// path must stay genuine fp32), stage acc+bias to smem, then threads 0..127
// advance the res/out oscillator recurrences 128 t-steps (state in regs
// across chunks) writing x_res_all/x_out_all directly. proj never exists in
// global memory (saves 512 MB of DRAM traffic + a kernel launch).
// Dyn smem (union, 67584 B -> 2 CTAs/SM):
//   mainloop: As [2][16][132] @ 0 | Bs [2][16][128] @ 4224 floats
//   epilogue: stage [128][132] @ 0
// ---------------------------------------------------------------------------
__global__ __launch_bounds__(256, 2) void k_fused_g1_osc(
        const float* __restrict__ A,     // x_in_all [B*T, 128]
        const float* __restrict__ Bm,    // proj_W [128, R]
        const float* __restrict__ bias,  // proj_b [R]
        const float* __restrict__ r_om, const float* __restrict__ r_ga,
        const float* __restrict__ r_al,
        const float* __restrict__ o_om, const float* __restrict__ o_ga,
        const float* __restrict__ o_al,
        float* __restrict__ x_res_all,
        float* __restrict__ x_out_all) {
    extern __shared__ float smf[];
    float* AsF = smf;                 // [2][16][132]
    float* BsF = smf + 2 * 16 * 132;  // [2][16][128]
    float* stage = smf;               // [128][132] (after mainloop, via sync)

    constexpr int N = R_;   // 2048
    constexpr int K = D_;   // 128
    const int tid = threadIdx.x;
    const int b = blockIdx.y;
    const int colBase = blockIdx.x * 128;

    // Oscillator params + persistent state (threads 0..127; r = colBase+tid)
    float rom2 = 0.f, rg2 = 0.f, ral = 0.f, oom2 = 0.f, og2 = 0.f, oal = 0.f;
    float xr = 0.f, yr = 0.f, xo = 0.f, yo = 0.f;
    if (tid < 128) {
        int r = colBase + tid;
        float v = fabsf(r_om[r]); rom2 = v * v;
        rg2 = 2.0f * fabsf(r_ga[r]);
        ral = r_al[r];
        v = fabsf(o_om[r]); oom2 = v * v;
        og2 = 2.0f * fabsf(o_ga[r]);
        oal = o_al[r];
    }

    const int aRow = tid >> 2;
    const int aCol = (tid & 3) * 4;
    const int bRow = tid >> 5;
    const int bCol = (tid & 31) * 4;
    const int tm = (tid >> 4) * 8;
    const int tn = (tid & 15) * 8;

    const float4 bz0 = *(const float4*)&bias[colBase + tn];
    const float4 bz1 = *(const float4*)&bias[colBase + tn + 4];

    const float* Bptr0 = Bm + (size_t)bRow * N + colBase + bCol;
    const float* Bptr1 = Bptr0 + (size_t)8 * N;

    float* xra = x_res_all + (size_t)b * T_ * R_ + colBase + tid;
    float* xoa = x_out_all + (size_t)b * T_ * R_ + colBase + tid;

    for (int tc = 0; tc < 4; tc++) {
        const int rowBase = b * T_ + tc * 128;
        const float* Aptr0 = A + (size_t)(rowBase + aRow) * K + aCol;
        const float* Aptr1 = Aptr0 + (size_t)64 * K;

        float acc[8][8] = {};
        float4 pa0, pa1, pb0, pb1;

        // prologue: chunk 0
        pa0 = *(const float4*)(Aptr0);
        pa1 = *(const float4*)(Aptr1);
        pb0 = *(const float4*)(Bptr0);
        pb1 = *(const float4*)(Bptr1);
        AsF[(aCol + 0) * 132 + aRow] = pa0.x;
        AsF[(aCol + 1) * 132 + aRow] = pa0.y;
        AsF[(aCol + 2) * 132 + aRow] = pa0.z;
        AsF[(aCol + 3) * 132 + aRow] = pa0.w;
        AsF[(aCol + 0) * 132 + aRow + 64] = pa1.x;
        AsF[(aCol + 1) * 132 + aRow + 64] = pa1.y;
        AsF[(aCol + 2) * 132 + aRow + 64] = pa1.z;
        AsF[(aCol + 3) * 132 + aRow + 64] = pa1.w;
        *(float4*)&BsF[bRow * 128 + bCol] = pb0;
        *(float4*)&BsF[(bRow + 8) * 128 + bCol] = pb1;
        __syncthreads();

        int buf = 0;
        for (int k0 = 0; k0 < K; k0 += 16) {
            const int knext = k0 + 16;
            if (knext < K) {
                pa0 = *(const float4*)(Aptr0 + knext);
                pa1 = *(const float4*)(Aptr1 + knext);
                pb0 = *(const float4*)(Bptr0 + (size_t)knext * N);
                pb1 = *(const float4*)(Bptr1 + (size_t)knext * N);
            }
            float* Asb = AsF + buf * 16 * 132;
            float* Bsb = BsF + buf * 16 * 128;
#pragma unroll
            for (int k = 0; k < 16; k++) {
                float4 ra0 = *(const float4*)&Asb[k * 132 + tm];
                float4 ra1 = *(const float4*)&Asb[k * 132 + tm + 4];
                float4 rb0 = *(const float4*)&Bsb[k * 128 + tn];
                float4 rb1 = *(const float4*)&Bsb[k * 128 + tn + 4];
                float ra[8] = {ra0.x, ra0.y, ra0.z, ra0.w, ra1.x, ra1.y, ra1.z, ra1.w};
                float rb[8] = {rb0.x, rb0.y, rb0.z, rb0.w, rb1.x, rb1.y, rb1.z, rb1.w};
#pragma unroll
                for (int i = 0; i < 8; i++)
#pragma unroll
                    for (int j = 0; j < 8; j++) acc[i][j] += ra[i] * rb[j];
            }
            if (knext < K) {
                const int nb = buf ^ 1;
                float* Asn = AsF + nb * 16 * 132;
                float* Bsn = BsF + nb * 16 * 128;
                Asn[(aCol + 0) * 132 + aRow] = pa0.x;
                Asn[(aCol + 1) * 132 + aRow] = pa0.y;
                Asn[(aCol + 2) * 132 + aRow] = pa0.z;
                Asn[(aCol + 3) * 132 + aRow] = pa0.w;
                Asn[(aCol + 0) * 132 + aRow + 64] = pa1.x;
                Asn[(aCol + 1) * 132 + aRow + 64] = pa1.y;
                Asn[(aCol + 2) * 132 + aRow + 64] = pa1.z;
                Asn[(aCol + 3) * 132 + aRow + 64] = pa1.w;
                *(float4*)&Bsn[bRow * 128 + bCol] = pb0;
                *(float4*)&Bsn[(bRow + 8) * 128 + bCol] = pb1;
                __syncthreads();
                buf = nb;
            }
        }
        __syncthreads();  // mainloop reads done; smem becomes stage

        // stage acc + bias (rows = t_local, cols = r within block)
#pragma unroll
        for (int i = 0; i < 8; i++) {
            float* sp = &stage[(tm + i) * 132 + tn];
            sp[0] = acc[i][0] + bz0.x;
            sp[1] = acc[i][1] + bz0.y;
            sp[2] = acc[i][2] + bz0.z;
            sp[3] = acc[i][3] + bz0.w;
            sp[4] = acc[i][4] + bz1.x;
            sp[5] = acc[i][5] + bz1.y;
            sp[6] = acc[i][6] + bz1.z;
            sp[7] = acc[i][7] + bz1.w;
        }
        __syncthreads();

        // recurrence over this chunk's 128 t-steps (threads 0..127)
        if (tid < 128) {
            float* xrp = xra + (size_t)(tc * 128) * R_;
            float* xop = xoa + (size_t)(tc * 128) * R_;
#pragma unroll 4
            for (int t = 0; t < 128; t++) {
                float f = stage[t * 132 + tid];
                float acr = ral * f - rg2 * yr - rom2 * xr;
                float xrn = clampf(xr + HSTEP * yr);
                float yrn = clampf(yr + HSTEP * acr);
                xr = xrn; yr = yrn;
                float aco = oal * xr - og2 * yo - oom2 * xo;
                float xon = clampf(xo + HSTEP * yo);
                float yon = clampf(yo + HSTEP * aco);
                xo = xon; yo = yon;
                xrp[t * R_] = xr;
                xop[t * R_] = xo;
            }
        }
        __syncthreads();  // stage free for next chunk's As/Bs
    }
}

// ---------------------------------------------------------------------------
// GEMM2: split-bf16 mma, 3 terms (tolerant readout path), single-stage smem,
// 2 CTAs/SM — r16-validated. C = A @ W + bias; W as bf16 hi/lo planes [N,K].
// ---------------------------------------------------------------------------
__global__ __launch_bounds__(256, 2) void gemm_mma_split_1s(const float* __restrict__ A,
                                                            const __nv_bfloat16* __restrict__ Bh,
                                                            const __nv_bfloat16* __restrict__ Bl,
                                                            const float* __restrict__ bias,
                                                            float* __restrict__ C,
                                                            int M, int N, int K) {
    extern __shared__ char smem[];
    const int tid  = threadIdx.x;
    const int wid  = tid >> 5;
    const int lane = tid & 31;
    const uint32_t sb = smem_u32(smem);
    const int rowBase = blockIdx.y * 128;
    const int colBase = blockIdx.x * 128;
    const int NCHUNK = K >> 6;  // K/64

    const uint32_t aH_b = sb;
    const uint32_t aL_b = sb + 16384;
    const uint32_t bH_b = sb + 32768;
    const uint32_t bL_b = sb + 49152;

    const int warpM = wid & 1;
    const int warpN = wid >> 1;
    const int g = lane >> 3;
    const int r = lane & 7;

    float acc[4][4][4] = {};

    const int aRow = warpM * 64 + (g & 1) * 8 + r;
    const int aKu  = (g >> 1);
    const int bRow = warpN * 32 + (g >> 1) * 8 + r;
    const int bKu  = (g & 1);

    for (int c = 0; c < NCHUNK; c++) {
        const int k0 = c << 6;
#pragma unroll
        for (int i = 0; i < 4; i++) {
            int u = tid + 256 * i;
            int row = u >> 3;
            int kc = (u & 7) * 8;
            const float4* src = (const float4*)(A + (size_t)(rowBase + row) * K + k0 + kc);
            float4 v0 = src[0], v1 = src[1];
            float vv[8] = {v0.x, v0.y, v0.z, v0.w, v1.x, v1.y, v1.z, v1.w};
            __nv_bfloat16 h[8], l[8];
#pragma unroll
            for (int j = 0; j < 8; j++) {
                h[j] = __float2bfloat16_rn(vv[j]);
                l[j] = __float2bfloat16_rn(vv[j] - __bfloat162float(h[j]));
            }
            uint32_t off = SWZ((uint32_t)(row * 128 + kc * 2));
            *(uint4*)(smem + off)         = *(const uint4*)h;
            *(uint4*)(smem + 16384 + off) = *(const uint4*)l;
        }
#pragma unroll
        for (int i = 0; i < 4; i++) {
            int ch = tid + 256 * i;
            int row = ch >> 3;
            int kc16 = ch & 7;
            uint32_t off = SWZ((uint32_t)(row * 128 + kc16 * 16));
            const char* sh = (const char*)(Bh + (size_t)(colBase + row) * K + k0) + kc16 * 16;
            const char* sl = (const char*)(Bl + (size_t)(colBase + row) * K + k0) + kc16 * 16;
            cp_async16(bH_b + off, sh);
            cp_async16(bL_b + off, sl);
        }
        CP_COMMIT();
        CP_WAIT(0);
        __syncthreads();

#pragma unroll
        for (int ks = 0; ks < 4; ks++) {
            uint32_t aH[4][4], aL[4][4];
            const int ku = ks * 2 + aKu;
#pragma unroll
            for (int mb = 0; mb < 4; mb++) {
                uint32_t off = SWZ((uint32_t)((aRow + mb * 16) * 128 + ku * 16));
                ldsm_x4(aH_b + off, aH[mb][0], aH[mb][1], aH[mb][2], aH[mb][3]);
                ldsm_x4(aL_b + off, aL[mb][0], aL[mb][1], aL[mb][2], aL[mb][3]);
            }
            const int bku = ks * 2 + bKu;
#pragma unroll
            for (int nbp = 0; nbp < 2; nbp++) {
                uint32_t bh[4], bl[4];
                uint32_t boff = SWZ((uint32_t)((bRow + nbp * 16) * 128 + bku * 16));
                ldsm_x4(bH_b + boff, bh[0], bh[1], bh[2], bh[3]);
                ldsm_x4(bL_b + boff, bl[0], bl[1], bl[2], bl[3]);
#pragma unroll
                for (int h = 0; h < 2; h++) {
                    const int nb = nbp * 2 + h;
#pragma unroll
                    for (int mb = 0; mb < 4; mb++) {
                        mma_bf16(acc[mb][nb], aH[mb], bh[h * 2], bh[h * 2 + 1]);
                        mma_bf16(acc[mb][nb], aH[mb], bl[h * 2], bl[h * 2 + 1]);
                        mma_bf16(acc[mb][nb], aL[mb], bh[h * 2], bh[h * 2 + 1]);
                    }
                }
            }
        }
        __syncthreads();
    }

    // epilogue: regs -> smem stage -> coalesced GMEM with bias
    float* stage = (float*)smem;  // [128][129]
    {
        const int mr = warpM * 64 + (lane >> 2);
        const int nc = warpN * 32 + (lane & 3) * 2;
#pragma unroll
        for (int mb = 0; mb < 4; mb++) {
#pragma unroll
            for (int nb = 0; nb < 4; nb++) {
                float* p0 = &stage[(mr + mb * 16) * 129 + nc + nb * 8];
                float* p1 = &stage[(mr + mb * 16 + 8) * 129 + nc + nb * 8];
                p0[0] = acc[mb][nb][0];
                p0[1] = acc[mb][nb][1];
                p1[0] = acc[mb][nb][2];
                p1[1] = acc[mb][nb][3];
            }
        }
    }
    __syncthreads();

    const int colL = tid & 127;
    const float bz = bias[colBase + colL];
#pragma unroll
    for (int r0 = tid >> 7; r0 < 128; r0 += 2)
        C[(size_t)(rowBase + r0) * N + colBase + colL] = stage[r0 * 129 + colL] + bz;
}

// ---------------------------------------------------------------------------
// Launch. Output layout: preds | x_in_all | x_res_all | x_out_all
// ---------------------------------------------------------------------------
extern "C" void kernel_launch(void* const* d_in, const int* in_sizes, int n_in,
                              void* d_out, int out_size) {
    const float* inputs   = (const float*)d_in[0];
    const float* in_omega = (const float*)d_in[1];
    const float* in_gamma = (const float*)d_in[2];
    const float* in_alpha = (const float*)d_in[3];
    const float* proj_W   = (const float*)d_in[4];
    const float* proj_b   = (const float*)d_in[5];
    const float* res_om   = (const float*)d_in[6];
    const float* res_ga   = (const float*)d_in[7];
    const float* res_al   = (const float*)d_in[8];
    const float* out_om   = (const float*)d_in[9];
    const float* out_ga   = (const float*)d_in[10];
    const float* out_al   = (const float*)d_in[11];
    const float* read_W   = (const float*)d_in[12];
    const float* read_b   = (const float*)d_in[13];

    float* out = (float*)d_out;
    const size_t BTD = (size_t)B_ * T_ * D_;
    const size_t BTR = (size_t)B_ * T_ * R_;
    float* preds     = out;
    float* x_in_all  = out + BTD;
    float* x_res_all = out + 2 * BTD;
    float* x_out_all = out + 2 * BTD + BTR;

    void* p;
    cudaGetSymbolAddress(&p, g_B2h);    __nv_bfloat16* B2h = (__nv_bfloat16*)p;
    cudaGetSymbolAddress(&p, g_B2l);    __nv_bfloat16* B2l = (__nv_bfloat16*)p;

    const int SMEM_F  = 128 * 132 * 4;  // 67584 (union: As+Bs | stage)
    const int SMEM_G2 = 128 * 129 * 4;  // 66048
    cudaFuncSetAttribute(k_fused_g1_osc, cudaFuncAttributeMaxDynamicSharedMemorySize, SMEM_F);
    cudaFuncSetAttribute(gemm_mma_split_1s, cudaFuncAttributeMaxDynamicSharedMemorySize, SMEM_G2);

    // Phase 1: input oscillators
    k_input_osc<<<(B_ * D_) / 256, 256>>>(inputs, in_omega, in_gamma, in_alpha, x_in_all);

    // read_W split (for GEMM2 only)
    k_split_bf16<<<(R_ * D_ + 255) / 256, 256>>>(read_W, B2h, B2l, R_, D_);

    // Fused GEMM1 + phase 3: (b, r-block) per CTA, 4 sequential t-chunks
    {
        dim3 grid(R_ / 128, B_);  // (16, 64) = 1024 CTAs
        k_fused_g1_osc<<<grid, 256, SMEM_F>>>(x_in_all, proj_W, proj_b,
                                              res_om, res_ga, res_al,
                                              out_om, out_ga, out_al,
                                              x_res_all, x_out_all);
    }

    // GEMM2 (split-bf16 tensor cores): preds = x_out @ read_W + read_b
    {
        dim3 grid(D_ / 128, (B_ * T_) / 128);  // (1, 256)
        gemm_mma_split_1s<<<grid, 256, SMEM_G2>>>(x_out_all, B2h, B2l, read_b, preds,
                                                  B_ * T_, D_, R_);
    }
}